// round 10
// baseline (speedup 1.0000x reference)
#include <cuda_runtime.h>
#include <cstdint>
#include <mma.h>

using namespace nvcuda;

static constexpr int NP   = 100000;     // points
static constexpr int NPAD = 100096;     // multiple of 128 (782 * 128)
static constexpr int CH   = 128;
static constexpr int HH   = 64;

// Scratch (device globals; referenced ONLY inside device code — never from host)
__device__ float g_y  [(size_t)NPAD * CH];   // y = x@w1 + b1   (tf32-rounded)
__device__ float g_r1 [(size_t)NPAD * HH];   // relu(sconv1)    (tf32-rounded)
__device__ float g_r2 [(size_t)NPAD * HH];   // relu(sconv2)    (tf32-rounded)
__device__ float g_w1r [CH * CH];            // rna(w1)
__device__ float g_w2r [CH * CH];            // rna(w2)
__device__ float g_rw1r[27 * HH * HH];       // rna(rw1) [k][c][d]
__device__ float g_rw2r[27 * HH * HH];       // rna(rw2) [k][c][d]

// ---------------------------------------------------------------------------
// helpers
// ---------------------------------------------------------------------------
__device__ __forceinline__ unsigned smem_u32(const void* p) {
    return (unsigned)__cvta_generic_to_shared(p);
}
__device__ __forceinline__ void cp16(unsigned dst, const void* src, int src_size) {
    asm volatile("cp.async.cg.shared.global [%0], [%1], 16, %2;"
                 :: "r"(dst), "l"(src), "r"(src_size));
}
__device__ __forceinline__ void cp_commit() { asm volatile("cp.async.commit_group;"); }
template <int N>
__device__ __forceinline__ void cp_wait() {
    asm volatile("cp.async.wait_group %0;" :: "n"(N));
}
__device__ __forceinline__ float rna_tf32(float x) {
    unsigned r;
    asm("cvt.rna.tf32.f32 %0, %1;" : "=r"(r) : "f"(x));
    return __uint_as_float(r);
}
__device__ __forceinline__ void mma_tf32(float* d, const uint32_t* a, const uint32_t* b) {
    asm volatile(
        "mma.sync.aligned.m16n8k8.row.col.f32.tf32.tf32.f32 "
        "{%0,%1,%2,%3}, {%4,%5,%6,%7}, {%8,%9}, {%0,%1,%2,%3};"
        : "+f"(d[0]), "+f"(d[1]), "+f"(d[2]), "+f"(d[3])
        : "r"(a[0]), "r"(a[1]), "r"(a[2]), "r"(a[3]), "r"(b[0]), "r"(b[1]));
}

// ---------------------------------------------------------------------------
// prologue: rna-rounded weight copies into device globals (read via symbols)
// ---------------------------------------------------------------------------
__global__ __launch_bounds__(256) void prep_weights(
    const float* __restrict__ w1, const float* __restrict__ w2,
    const float* __restrict__ rw1, const float* __restrict__ rw2)
{
    int j = blockIdx.x * 256 + threadIdx.x;
    if (j < CH * CH) {
        g_w1r[j] = rna_tf32(w1[j]);
        g_w2r[j] = rna_tf32(w2[j]);
    }
    if (j < 27 * HH * HH) {
        g_rw1r[j] = rna_tf32(rw1[j]);
        g_rw2r[j] = rna_tf32(rw2[j]);
    }
}

// ---------------------------------------------------------------------------
// GEMM1: g_y[n,:] = rna( x[n,:] @ rna(w1) + b1 )
// 64-row tiles, N split into two 64-col halves through ONE reused B buffer.
// smem = As 64x132 + Bs 128x68 = 68608 B -> 3 CTAs/SM.
// ---------------------------------------------------------------------------
__global__ __launch_bounds__(256, 3) void gemm1_kernel(
    const float* __restrict__ x, const float* __restrict__ b1)
{
    extern __shared__ float smem[];
    float* As = smem;               // 64 x 132
    float* Bs = smem + 64 * 132;    // 128 x 68 (one 64-col half of w1)

    const int tid = threadIdx.x;
    const int rowBase = blockIdx.x * 64;
    const int warp = tid >> 5;
    const int mw = warp >> 1, nw = warp & 1;   // 4 x 2: 16 rows x 32 cols (per half)

    // A tile (x) + B half 0
    #pragma unroll
    for (int i = 0; i < 8; i++) {
        int j = tid + i * 256;
        int row = j >> 5, seg = j & 31;
        int n = rowBase + row;
        cp16(smem_u32(As + row * 132 + seg * 4), x + (size_t)n * 128 + seg * 4,
             (n < NP) ? 16 : 0);
    }
    #pragma unroll
    for (int i = 0; i < 8; i++) {
        int j = tid + i * 256;                 // 0..2047 -> 128 rows x 16 chunks
        int row = j >> 4, seg = j & 15;
        cp16(smem_u32(Bs + row * 68 + seg * 4), g_w1r + row * 128 + seg * 4, 16);
    }
    cp_commit();
    cp_wait<0>();
    __syncthreads();

    wmma::fragment<wmma::accumulator, 16, 16, 8, float> c[2][2];
    #pragma unroll
    for (int h = 0; h < 2; h++)
        #pragma unroll
        for (int f = 0; f < 2; f++) wmma::fill_fragment(c[h][f], 0.f);

    #pragma unroll
    for (int kk = 0; kk < 16; kk++) {
        wmma::fragment<wmma::matrix_a, 16, 16, 8, wmma::precision::tf32, wmma::row_major> a;
        wmma::load_matrix_sync(a, As + (mw * 16) * 132 + kk * 8, 132);
        #pragma unroll
        for (int f = 0; f < 2; f++) {
            wmma::fragment<wmma::matrix_b, 16, 16, 8, wmma::precision::tf32, wmma::row_major> b;
            wmma::load_matrix_sync(b, Bs + (kk * 8) * 68 + nw * 32 + f * 16, 68);
            wmma::mma_sync(c[0][f], a, b, c[0][f]);
        }
    }
    __syncthreads();                           // done reading Bs half 0

    // B half 1
    #pragma unroll
    for (int i = 0; i < 8; i++) {
        int j = tid + i * 256;
        int row = j >> 4, seg = j & 15;
        cp16(smem_u32(Bs + row * 68 + seg * 4), g_w1r + row * 128 + 64 + seg * 4, 16);
    }
    cp_commit();
    cp_wait<0>();
    __syncthreads();

    #pragma unroll
    for (int kk = 0; kk < 16; kk++) {
        wmma::fragment<wmma::matrix_a, 16, 16, 8, wmma::precision::tf32, wmma::row_major> a;
        wmma::load_matrix_sync(a, As + (mw * 16) * 132 + kk * 8, 132);
        #pragma unroll
        for (int f = 0; f < 2; f++) {
            wmma::fragment<wmma::matrix_b, 16, 16, 8, wmma::precision::tf32, wmma::row_major> b;
            wmma::load_matrix_sync(b, Bs + (kk * 8) * 68 + nw * 32 + f * 16, 68);
            wmma::mma_sync(c[1][f], a, b, c[1][f]);
        }
    }
    __syncthreads();                           // done reading As before frag store

    #pragma unroll
    for (int h = 0; h < 2; h++)
        #pragma unroll
        for (int f = 0; f < 2; f++)
            wmma::store_matrix_sync(As + (mw * 16) * 132 + h * 64 + nw * 32 + f * 16,
                                    c[h][f], 132, wmma::mem_row_major);
    __syncthreads();

    #pragma unroll
    for (int i = 0; i < 8; i++) {
        int j = tid + i * 256;
        int row = j >> 5, seg = j & 31;
        int n = rowBase + row;
        float4 v  = *(float4*)(As + row * 132 + seg * 4);
        float4 bb = *(const float4*)(b1 + seg * 4);
        v.x = rna_tf32(v.x + bb.x);
        v.y = rna_tf32(v.y + bb.y);
        v.z = rna_tf32(v.z + bb.z);
        v.w = rna_tf32(v.w + bb.w);
        *(float4*)(g_y + (size_t)n * 128 + seg * 4) = v;
    }
}

// ---------------------------------------------------------------------------
// sconv (raw mma.sync m16n8k8 tf32) — R9-proven structure, unchanged except:
// weights read from rna-rounded device symbol; epilogue adds rna.
// ---------------------------------------------------------------------------
template <int SRC>
__global__ __launch_bounds__(256, 2) void sconv_mma(
    const int*   __restrict__ nbr,
    const float* __restrict__ rb)
{
    extern __shared__ float sm[];

    const float* feat = (SRC == 0) ? g_y : g_r1;
    const float* rwp  = (SRC == 0) ? g_rw1r : g_rw2r;
    float*       outp = (SRC == 0) ? g_r1 : g_r2;
    const int    ldf  = (SRC == 0) ? 128 : 64;

    const int tid  = threadIdx.x;
    const int lane = tid & 31;
    const int warp = tid >> 5;
    const int wrow = warp >> 1;          // 0..3 -> rows 32*wrow
    const int wcol = warp & 1;           // 0..1 -> cols 32*wcol
    const int lr   = lane >> 2;          // 0..7
    const int la3  = lane & 3;           // 0..3
    const int rowBase = blockIdx.x * 128;

    const int arow  = tid >> 1;          // 0..127
    const int ahalf = tid & 1;           // halves (32 floats)
    const int brow  = tid >> 2;          // 0..63 (B row = c)
    const int bq    = tid & 3;           // quarter (16 floats)
    const int an    = rowBase + arow;

    auto ldIdx = [&](int kk) -> int {
        return (an < NP) ? __ldg(nbr + (size_t)kk * NP + an) : -1;
    };
    auto fillA = [&](int buf, int idx) {
        int sz = (idx >= 0) ? 16 : 0;
        const float* src = feat + (size_t)(idx < 0 ? 0 : idx) * ldf + ahalf * 32;
        unsigned d = smem_u32(sm + buf * 8704 + arow * 68 + ahalf * 32);
        #pragma unroll
        for (int s = 0; s < 8; s++)
            cp16(d + (unsigned)(s * 16), src + s * 4, sz);
    };
    auto fillB = [&](int kk, int buf) {
        const float* src = rwp + (size_t)kk * 4096 + brow * 64 + bq * 16;
        unsigned d = smem_u32(sm + 17408 + buf * 4608 + brow * 72 + bq * 16);
        #pragma unroll
        for (int s = 0; s < 4; s++)
            cp16(d + (unsigned)(s * 16), src + s * 4, 16);
    };

    float acc[2][4][4];
    #pragma unroll
    for (int mt = 0; mt < 2; mt++)
        #pragma unroll
        for (int nt = 0; nt < 4; nt++)
            #pragma unroll
            for (int q = 0; q < 4; q++) acc[mt][nt][q] = 0.f;

    int rr[4];
    #pragma unroll
    for (int i = 0; i < 4; i++) rr[i] = wrow * 32 + lr + i * 8;

    int idxNxt = ldIdx(0);
    fillA(0, idxNxt);
    fillB(0, 0);
    cp_commit();
    idxNxt = ldIdx(1);

    for (int kk = 0; kk < 27; kk++) {
        const int buf = kk & 1;
        if (kk + 1 < 27) {
            fillA(buf ^ 1, idxNxt);
            fillB(kk + 1, buf ^ 1);
            cp_commit();
            if (kk + 2 < 27) idxNxt = ldIdx(kk + 2);
            cp_wait<1>();
        } else {
            cp_wait<0>();
        }
        __syncthreads();

        const float* Ab = sm + buf * 8704;
        const float* Bb = sm + 17408 + buf * 4608;

        #pragma unroll
        for (int k8 = 0; k8 < 8; k8++) {
            uint32_t af[4][2];
            #pragma unroll
            for (int i = 0; i < 4; i++) {
                int r = rr[i];
                af[i][0] = __float_as_uint(Ab[r * 68 + k8 * 8 + la3]);
                af[i][1] = __float_as_uint(Ab[r * 68 + k8 * 8 + 4 + la3]);
            }
            uint32_t bf[4][2];
            #pragma unroll
            for (int nt = 0; nt < 4; nt++) {
                int n = wcol * 32 + nt * 8 + lr;
                bf[nt][0] = __float_as_uint(Bb[(k8 * 8 + la3)     * 72 + n]);
                bf[nt][1] = __float_as_uint(Bb[(k8 * 8 + 4 + la3) * 72 + n]);
            }
            #pragma unroll
            for (int mt = 0; mt < 2; mt++) {
                uint32_t a[4] = { af[2 * mt][0], af[2 * mt + 1][0],
                                  af[2 * mt][1], af[2 * mt + 1][1] };
                #pragma unroll
                for (int nt = 0; nt < 4; nt++)
                    mma_tf32(acc[mt][nt], a, bf[nt]);
            }
        }
        __syncthreads();
    }

    // epilogue: bias + relu + rna, register -> global
    #pragma unroll
    for (int nt = 0; nt < 4; nt++) {
        int cc = wcol * 32 + nt * 8 + 2 * la3;
        float rb0 = rb[cc], rb1 = rb[cc + 1];
        #pragma unroll
        for (int mt = 0; mt < 2; mt++) {
            int r0 = rowBase + wrow * 32 + mt * 16 + lr;
            float2 v0, v1;
            v0.x = rna_tf32(fmaxf(acc[mt][nt][0] + rb0, 0.f));
            v0.y = rna_tf32(fmaxf(acc[mt][nt][1] + rb1, 0.f));
            v1.x = rna_tf32(fmaxf(acc[mt][nt][2] + rb0, 0.f));
            v1.y = rna_tf32(fmaxf(acc[mt][nt][3] + rb1, 0.f));
            *(float2*)(outp + (size_t)r0 * 64 + cc)       = v0;
            *(float2*)(outp + (size_t)(r0 + 8) * 64 + cc) = v1;
        }
    }
}

// ---------------------------------------------------------------------------
// GEMM2: out = x + concat(rna(r2 + 2*y[:,:64]), y[:,64:]) @ rna(w2) + b2
// Same N-split structure as GEMM1 -> 3 CTAs/SM.
// ---------------------------------------------------------------------------
__global__ __launch_bounds__(256, 3) void gemm2_kernel(
    const float* __restrict__ x, const float* __restrict__ b2,
    float* __restrict__ out)
{
    extern __shared__ float smem[];
    float* As = smem;               // 64 x 132
    float* Bs = smem + 64 * 132;    // 128 x 68

    const int tid = threadIdx.x;
    const int rowBase = blockIdx.x * 64;
    const int warp = tid >> 5;
    const int mw = warp >> 1, nw = warp & 1;

    // B half 0 (async) while building A in registers
    #pragma unroll
    for (int i = 0; i < 8; i++) {
        int j = tid + i * 256;
        int row = j >> 4, seg = j & 15;
        cp16(smem_u32(Bs + row * 68 + seg * 4), g_w2r + row * 128 + seg * 4, 16);
    }
    cp_commit();

    #pragma unroll
    for (int i = 0; i < 8; i++) {
        int j = tid + i * 256;
        int row = j >> 5, seg = j & 31;
        int n = rowBase + row;
        float4 v;
        if (seg < 16) {
            float4 r = *(const float4*)(g_r2 + (size_t)n * 64  + seg * 4);
            float4 y = *(const float4*)(g_y  + (size_t)n * 128 + seg * 4);
            v.x = rna_tf32(fmaf(2.f, y.x, r.x));
            v.y = rna_tf32(fmaf(2.f, y.y, r.y));
            v.z = rna_tf32(fmaf(2.f, y.z, r.z));
            v.w = rna_tf32(fmaf(2.f, y.w, r.w));
        } else {
            v = *(const float4*)(g_y + (size_t)n * 128 + seg * 4);
        }
        *(float4*)(As + row * 132 + seg * 4) = v;
    }
    cp_wait<0>();
    __syncthreads();

    wmma::fragment<wmma::accumulator, 16, 16, 8, float> c[2][2];
    #pragma unroll
    for (int h = 0; h < 2; h++)
        #pragma unroll
        for (int f = 0; f < 2; f++) wmma::fill_fragment(c[h][f], 0.f);

    #pragma unroll
    for (int kk = 0; kk < 16; kk++) {
        wmma::fragment<wmma::matrix_a, 16, 16, 8, wmma::precision::tf32, wmma::row_major> a;
        wmma::load_matrix_sync(a, As + (mw * 16) * 132 + kk * 8, 132);
        #pragma unroll
        for (int f = 0; f < 2; f++) {
            wmma::fragment<wmma::matrix_b, 16, 16, 8, wmma::precision::tf32, wmma::row_major> b;
            wmma::load_matrix_sync(b, Bs + (kk * 8) * 68 + nw * 32 + f * 16, 68);
            wmma::mma_sync(c[0][f], a, b, c[0][f]);
        }
    }
    __syncthreads();

    #pragma unroll
    for (int i = 0; i < 8; i++) {
        int j = tid + i * 256;
        int row = j >> 4, seg = j & 15;
        cp16(smem_u32(Bs + row * 68 + seg * 4), g_w2r + row * 128 + 64 + seg * 4, 16);
    }
    cp_commit();
    cp_wait<0>();
    __syncthreads();

    #pragma unroll
    for (int kk = 0; kk < 16; kk++) {
        wmma::fragment<wmma::matrix_a, 16, 16, 8, wmma::precision::tf32, wmma::row_major> a;
        wmma::load_matrix_sync(a, As + (mw * 16) * 132 + kk * 8, 132);
        #pragma unroll
        for (int f = 0; f < 2; f++) {
            wmma::fragment<wmma::matrix_b, 16, 16, 8, wmma::precision::tf32, wmma::row_major> b;
            wmma::load_matrix_sync(b, Bs + (kk * 8) * 68 + nw * 32 + f * 16, 68);
            wmma::mma_sync(c[1][f], a, b, c[1][f]);
        }
    }
    __syncthreads();

    #pragma unroll
    for (int h = 0; h < 2; h++)
        #pragma unroll
        for (int f = 0; f < 2; f++)
            wmma::store_matrix_sync(As + (mw * 16) * 132 + h * 64 + nw * 32 + f * 16,
                                    c[h][f], 132, wmma::mem_row_major);
    __syncthreads();

    #pragma unroll
    for (int i = 0; i < 8; i++) {
        int j = tid + i * 256;
        int row = j >> 5, seg = j & 31;
        int n = rowBase + row;
        if (n < NP) {
            float4 v  = *(float4*)(As + row * 132 + seg * 4);
            float4 bb = *(const float4*)(b2 + seg * 4);
            float4 xr = *(const float4*)(x + (size_t)n * 128 + seg * 4);
            v.x += bb.x + xr.x;
            v.y += bb.y + xr.y;
            v.z += bb.z + xr.z;
            v.w += bb.w + xr.w;
            *(float4*)(out + (size_t)n * 128 + seg * 4) = v;
        }
    }
}

// ---------------------------------------------------------------------------
extern "C" void kernel_launch(void* const* d_in, const int* in_sizes, int n_in,
                              void* d_out, int out_size)
{
    const float* x   = (const float*)d_in[0];
    const float* w1  = (const float*)d_in[1];
    const float* b1  = (const float*)d_in[2];
    const float* w2  = (const float*)d_in[3];
    const float* b2  = (const float*)d_in[4];
    const float* rw1 = (const float*)d_in[5];
    const float* rb1 = (const float*)d_in[6];
    const float* rw2 = (const float*)d_in[7];
    const float* rb2 = (const float*)d_in[8];
    const int*   nbr = (const int*)  d_in[9];
    float* out = (float*)d_out;

    const int SMEM_G = (64 * 132 + 128 * 68) * (int)sizeof(float);        // 68608 B
    const int SMEM_S = (2 * 128 * 68 + 2 * 64 * 72) * (int)sizeof(float); // 106496 B
    static bool attr_done = false;
    if (!attr_done) {
        cudaFuncSetAttribute(gemm1_kernel, cudaFuncAttributeMaxDynamicSharedMemorySize, SMEM_G);
        cudaFuncSetAttribute(gemm2_kernel, cudaFuncAttributeMaxDynamicSharedMemorySize, SMEM_G);
        cudaFuncSetAttribute(sconv_mma<0>, cudaFuncAttributeMaxDynamicSharedMemorySize, SMEM_S);
        cudaFuncSetAttribute(sconv_mma<1>, cudaFuncAttributeMaxDynamicSharedMemorySize, SMEM_S);
        attr_done = true;
    }

    const int gridG = NPAD / 64;    // 1564
    const int gridS = NPAD / 128;   // 782

    prep_weights<<<432, 256>>>(w1, w2, rw1, rw2);
    gemm1_kernel<<<gridG, 256, SMEM_G>>>(x, b1);
    sconv_mma<0><<<gridS, 256, SMEM_S>>>(nbr, rb1);
    sconv_mma<1><<<gridS, 256, SMEM_S>>>(nbr, rb2);
    gemm2_kernel<<<gridG, 256, SMEM_G>>>(x, b2, out);
}

// round 11
// speedup vs baseline: 1.3150x; 1.3150x over previous
#include <cuda_runtime.h>
#include <cstdint>
#include <mma.h>

using namespace nvcuda;

static constexpr int NP   = 100000;     // points
static constexpr int NPAD = 100096;     // multiple of 128 (782 * 128)
static constexpr int CH   = 128;
static constexpr int HH   = 64;

// Scratch (device globals; referenced ONLY inside device code — never from host)
__device__ float g_y  [(size_t)NPAD * CH];   // y = x@w1 + b1   (tf32-rounded)
__device__ float g_r1 [(size_t)NPAD * HH];   // relu(sconv1)    (tf32-rounded)
__device__ float g_r2 [(size_t)NPAD * HH];   // relu(sconv2)    (tf32-rounded)
__device__ float g_w1r [CH * CH];            // rna(w1)
__device__ float g_w2r [CH * CH];            // rna(w2)
__device__ float g_rwp1[27 * HH * HH];       // rna(rw1) TRANSPOSED: [k][d][c]
__device__ float g_rwp2[27 * HH * HH];       // rna(rw2) TRANSPOSED: [k][d][c]

// ---------------------------------------------------------------------------
// helpers
// ---------------------------------------------------------------------------
__device__ __forceinline__ unsigned smem_u32(const void* p) {
    return (unsigned)__cvta_generic_to_shared(p);
}
__device__ __forceinline__ void cp16(unsigned dst, const void* src, int src_size) {
    asm volatile("cp.async.cg.shared.global [%0], [%1], 16, %2;"
                 :: "r"(dst), "l"(src), "r"(src_size));
}
__device__ __forceinline__ void cp_commit() { asm volatile("cp.async.commit_group;"); }
template <int N>
__device__ __forceinline__ void cp_wait() {
    asm volatile("cp.async.wait_group %0;" :: "n"(N));
}
__device__ __forceinline__ float rna_tf32(float x) {
    unsigned r;
    asm("cvt.rna.tf32.f32 %0, %1;" : "=r"(r) : "f"(x));
    return __uint_as_float(r);
}
__device__ __forceinline__ void mma_tf32(float* d, const uint32_t* a, const uint32_t* b) {
    asm volatile(
        "mma.sync.aligned.m16n8k8.row.col.f32.tf32.tf32.f32 "
        "{%0,%1,%2,%3}, {%4,%5,%6,%7}, {%8,%9}, {%0,%1,%2,%3};"
        : "+f"(d[0]), "+f"(d[1]), "+f"(d[2]), "+f"(d[3])
        : "r"(a[0]), "r"(a[1]), "r"(a[2]), "r"(a[3]), "r"(b[0]), "r"(b[1]));
}

// ---------------------------------------------------------------------------
// prologue: rna weight copies; sconv weights transposed to [k][d][c]
// ---------------------------------------------------------------------------
__global__ __launch_bounds__(256) void prep_weights(
    const float* __restrict__ w1, const float* __restrict__ w2,
    const float* __restrict__ rw1, const float* __restrict__ rw2)
{
    int j = blockIdx.x * 256 + threadIdx.x;
    if (j < CH * CH) {
        g_w1r[j] = rna_tf32(w1[j]);
        g_w2r[j] = rna_tf32(w2[j]);
    }
    if (j < 27 * HH * HH) {
        int k = j >> 12, d = (j >> 6) & 63, c = j & 63;
        int src = (k << 12) + (c << 6) + d;
        g_rwp1[j] = rna_tf32(rw1[src]);
        g_rwp2[j] = rna_tf32(rw2[src]);
    }
}

// ---------------------------------------------------------------------------
// GEMM1 (R9-proven structure): g_y[n,:] = rna( x[n,:] @ rna(w1) + b1 )
// ---------------------------------------------------------------------------
__global__ __launch_bounds__(256) void gemm1_kernel(
    const float* __restrict__ x, const float* __restrict__ b1)
{
    extern __shared__ float smem[];
    float* As = smem;               // 64 x 132
    float* Bs = smem + 64 * 132;    // 128 x 132

    const int tid = threadIdx.x;
    const int rowBase = blockIdx.x * 64;

    #pragma unroll
    for (int i = 0; i < 8; i++) {
        int j = tid + i * 256;
        int row = j >> 5, seg = j & 31;
        int n = rowBase + row;
        cp16(smem_u32(As + row * 132 + seg * 4), x + (size_t)n * 128 + seg * 4,
             (n < NP) ? 16 : 0);
    }
    #pragma unroll
    for (int i = 0; i < 16; i++) {
        int j = tid + i * 256;
        int row = j >> 5, seg = j & 31;
        cp16(smem_u32(Bs + row * 132 + seg * 4), g_w1r + j * 4, 16);
    }
    cp_commit();
    cp_wait<0>();
    __syncthreads();

    const int warp = tid >> 5;
    const int mw = warp >> 1, nw = warp & 1;

    wmma::fragment<wmma::accumulator, 16, 16, 8, float> c[4];
    #pragma unroll
    for (int f = 0; f < 4; f++) wmma::fill_fragment(c[f], 0.f);

    #pragma unroll
    for (int kk = 0; kk < 16; kk++) {
        wmma::fragment<wmma::matrix_a, 16, 16, 8, wmma::precision::tf32, wmma::row_major> a;
        wmma::load_matrix_sync(a, As + (mw * 16) * 132 + kk * 8, 132);
        #pragma unroll
        for (int f = 0; f < 4; f++) {
            wmma::fragment<wmma::matrix_b, 16, 16, 8, wmma::precision::tf32, wmma::row_major> b;
            wmma::load_matrix_sync(b, Bs + (kk * 8) * 132 + nw * 64 + f * 16, 132);
            wmma::mma_sync(c[f], a, b, c[f]);
        }
    }
    __syncthreads();
    #pragma unroll
    for (int f = 0; f < 4; f++)
        wmma::store_matrix_sync(As + (mw * 16) * 132 + nw * 64 + f * 16, c[f], 132,
                                wmma::mem_row_major);
    __syncthreads();

    #pragma unroll
    for (int i = 0; i < 8; i++) {
        int j = tid + i * 256;
        int row = j >> 5, seg = j & 31;
        int n = rowBase + row;
        float4 v  = *(float4*)(As + row * 132 + seg * 4);
        float4 bb = *(const float4*)(b1 + seg * 4);
        v.x = rna_tf32(v.x + bb.x);
        v.y = rna_tf32(v.y + bb.y);
        v.z = rna_tf32(v.z + bb.z);
        v.w = rna_tf32(v.w + bb.w);
        *(float4*)(g_y + (size_t)n * 128 + seg * 4) = v;
    }
}

// ---------------------------------------------------------------------------
// sconv (raw mma.sync m16n8k8 tf32, paired float2 fragment loads):
//   out[n,0:64] = rna(relu( sum_k feat[nbr[k,n]] @ rw[k] + rb ))
// MMA-k slot kappa reads A position pi(kappa) (pi = pair interleave); B is
// pre-transposed [k][d][c] so the same position holds the matching weight —
// contraction is a permutation of channels, numerically equivalent.
// A smem [128][72], B smem [64][72]: float2 loads, uniform 2-way (optimal).
// ONE __syncthreads per iteration: fills issued after the barrier.
// smem: A[2][128][72] + B[2][64][72] = 110592 B -> 2 CTAs/SM.
// ---------------------------------------------------------------------------
template <int SRC>
__global__ __launch_bounds__(256, 2) void sconv_mma(
    const int*   __restrict__ nbr,
    const float* __restrict__ rb)
{
    extern __shared__ float sm[];

    const float* feat = (SRC == 0) ? g_y : g_r1;
    const float* rwp  = (SRC == 0) ? g_rwp1 : g_rwp2;
    float*       outp = (SRC == 0) ? g_r1 : g_r2;
    const int    ldf  = (SRC == 0) ? 128 : 64;

    const int tid  = threadIdx.x;
    const int lane = tid & 31;
    const int warp = tid >> 5;
    const int wrow = warp >> 1;          // 0..3 -> rows 32*wrow
    const int wcol = warp & 1;           // 0..1 -> cols 32*wcol
    const int lr   = lane >> 2;          // 0..7
    const int la3  = lane & 3;           // 0..3
    const int rowBase = blockIdx.x * 128;

    const int arow  = tid >> 1;          // 0..127
    const int ahalf = tid & 1;           // halves (32 floats)
    const int brow  = tid >> 2;          // 0..63 (B row = d)
    const int bq    = tid & 3;           // quarter (16 floats)
    const int an    = rowBase + arow;

    auto ldIdx = [&](int kk) -> int {
        return (an < NP) ? __ldg(nbr + (size_t)kk * NP + an) : -1;
    };
    auto fillA = [&](int buf, int idx) {
        int sz = (idx >= 0) ? 16 : 0;
        const float* src = feat + (size_t)(idx < 0 ? 0 : idx) * ldf + ahalf * 32;
        unsigned d = smem_u32(sm + buf * 9216 + arow * 72 + ahalf * 32);
        #pragma unroll
        for (int s = 0; s < 8; s++)
            cp16(d + (unsigned)(s * 16), src + s * 4, sz);
    };
    auto fillB = [&](int kk, int buf) {
        const float* src = rwp + (size_t)kk * 4096 + brow * 64 + bq * 16;
        unsigned d = smem_u32(sm + 18432 + buf * 4608 + brow * 72 + bq * 16);
        #pragma unroll
        for (int s = 0; s < 4; s++)
            cp16(d + (unsigned)(s * 16), src + s * 4, 16);
    };

    float acc[2][4][4];
    #pragma unroll
    for (int mt = 0; mt < 2; mt++)
        #pragma unroll
        for (int nt = 0; nt < 4; nt++)
            #pragma unroll
            for (int q = 0; q < 4; q++) acc[mt][nt][q] = 0.f;

    int rr[4];
    #pragma unroll
    for (int i = 0; i < 4; i++) rr[i] = wrow * 32 + lr + i * 8;

    int idxNxt = ldIdx(0);
    fillA(0, idxNxt);
    fillB(0, 0);
    cp_commit();
    idxNxt = ldIdx(1);

    for (int kk = 0; kk < 27; kk++) {
        const int buf = kk & 1;
        cp_wait<0>();                    // stage kk copies (this thread) done
        __syncthreads();                 // all threads' copies visible; prev readers done

        if (kk + 1 < 27) {               // fills AFTER barrier -> safe buffer recycle
            fillA(buf ^ 1, idxNxt);
            fillB(kk + 1, buf ^ 1);
            cp_commit();
            if (kk + 2 < 27) idxNxt = ldIdx(kk + 2);
        }

        const float* Ab = sm + buf * 9216;
        const float* Bb = sm + 18432 + buf * 4608;

        #pragma unroll
        for (int k8 = 0; k8 < 8; k8++) {
            uint32_t af[4][2];
            #pragma unroll
            for (int i = 0; i < 4; i++) {
                float2 t = *(const float2*)(Ab + rr[i] * 72 + k8 * 8 + 2 * la3);
                af[i][0] = __float_as_uint(t.x);
                af[i][1] = __float_as_uint(t.y);
            }
            uint32_t bf[4][2];
            #pragma unroll
            for (int nt = 0; nt < 4; nt++) {
                int n = wcol * 32 + nt * 8 + lr;
                float2 t = *(const float2*)(Bb + n * 72 + k8 * 8 + 2 * la3);
                bf[nt][0] = __float_as_uint(t.x);
                bf[nt][1] = __float_as_uint(t.y);
            }
            #pragma unroll
            for (int mt = 0; mt < 2; mt++) {
                uint32_t a[4] = { af[2 * mt][0], af[2 * mt + 1][0],
                                  af[2 * mt][1], af[2 * mt + 1][1] };
                #pragma unroll
                for (int nt = 0; nt < 4; nt++)
                    mma_tf32(acc[mt][nt], a, bf[nt]);
            }
        }
    }

    // epilogue: bias + relu + rna, register -> global
    #pragma unroll
    for (int nt = 0; nt < 4; nt++) {
        int cc = wcol * 32 + nt * 8 + 2 * la3;
        float rb0 = rb[cc], rb1 = rb[cc + 1];
        #pragma unroll
        for (int mt = 0; mt < 2; mt++) {
            int r0 = rowBase + wrow * 32 + mt * 16 + lr;
            float2 v0, v1;
            v0.x = rna_tf32(fmaxf(acc[mt][nt][0] + rb0, 0.f));
            v0.y = rna_tf32(fmaxf(acc[mt][nt][1] + rb1, 0.f));
            v1.x = rna_tf32(fmaxf(acc[mt][nt][2] + rb0, 0.f));
            v1.y = rna_tf32(fmaxf(acc[mt][nt][3] + rb1, 0.f));
            *(float2*)(outp + (size_t)r0 * 64 + cc)       = v0;
            *(float2*)(outp + (size_t)(r0 + 8) * 64 + cc) = v1;
        }
    }
}

// ---------------------------------------------------------------------------
// GEMM2 (R9-proven structure): out = x + concat(rna(r2+2*yc), yt) @ rna(w2) + b2
// ---------------------------------------------------------------------------
__global__ __launch_bounds__(256) void gemm2_kernel(
    const float* __restrict__ x, const float* __restrict__ b2,
    float* __restrict__ out)
{
    extern __shared__ float smem[];
    float* As = smem;
    float* Bs = smem + 64 * 132;

    const int tid = threadIdx.x;
    const int rowBase = blockIdx.x * 64;

    #pragma unroll
    for (int i = 0; i < 16; i++) {
        int j = tid + i * 256;
        int row = j >> 5, seg = j & 31;
        cp16(smem_u32(Bs + row * 132 + seg * 4), g_w2r + j * 4, 16);
    }
    cp_commit();

    #pragma unroll
    for (int i = 0; i < 8; i++) {
        int j = tid + i * 256;
        int row = j >> 5, seg = j & 31;
        int n = rowBase + row;
        float4 v;
        if (seg < 16) {
            float4 r = *(const float4*)(g_r2 + (size_t)n * 64  + seg * 4);
            float4 y = *(const float4*)(g_y  + (size_t)n * 128 + seg * 4);
            v.x = rna_tf32(fmaf(2.f, y.x, r.x));
            v.y = rna_tf32(fmaf(2.f, y.y, r.y));
            v.z = rna_tf32(fmaf(2.f, y.z, r.z));
            v.w = rna_tf32(fmaf(2.f, y.w, r.w));
        } else {
            v = *(const float4*)(g_y + (size_t)n * 128 + seg * 4);
        }
        *(float4*)(As + row * 132 + seg * 4) = v;
    }
    cp_wait<0>();
    __syncthreads();

    const int warp = tid >> 5;
    const int mw = warp >> 1, nw = warp & 1;

    wmma::fragment<wmma::accumulator, 16, 16, 8, float> c[4];
    #pragma unroll
    for (int f = 0; f < 4; f++) wmma::fill_fragment(c[f], 0.f);

    #pragma unroll
    for (int kk = 0; kk < 16; kk++) {
        wmma::fragment<wmma::matrix_a, 16, 16, 8, wmma::precision::tf32, wmma::row_major> a;
        wmma::load_matrix_sync(a, As + (mw * 16) * 132 + kk * 8, 132);
        #pragma unroll
        for (int f = 0; f < 4; f++) {
            wmma::fragment<wmma::matrix_b, 16, 16, 8, wmma::precision::tf32, wmma::row_major> b;
            wmma::load_matrix_sync(b, Bs + (kk * 8) * 132 + nw * 64 + f * 16, 132);
            wmma::mma_sync(c[f], a, b, c[f]);
        }
    }
    __syncthreads();
    #pragma unroll
    for (int f = 0; f < 4; f++)
        wmma::store_matrix_sync(As + (mw * 16) * 132 + nw * 64 + f * 16, c[f], 132,
                                wmma::mem_row_major);
    __syncthreads();

    #pragma unroll
    for (int i = 0; i < 8; i++) {
        int j = tid + i * 256;
        int row = j >> 5, seg = j & 31;
        int n = rowBase + row;
        if (n < NP) {
            float4 v  = *(float4*)(As + row * 132 + seg * 4);
            float4 bb = *(const float4*)(b2 + seg * 4);
            float4 xr = *(const float4*)(x + (size_t)n * 128 + seg * 4);
            v.x += bb.x + xr.x;
            v.y += bb.y + xr.y;
            v.z += bb.z + xr.z;
            v.w += bb.w + xr.w;
            *(float4*)(out + (size_t)n * 128 + seg * 4) = v;
        }
    }
}

// ---------------------------------------------------------------------------
extern "C" void kernel_launch(void* const* d_in, const int* in_sizes, int n_in,
                              void* d_out, int out_size)
{
    const float* x   = (const float*)d_in[0];
    const float* w1  = (const float*)d_in[1];
    const float* b1  = (const float*)d_in[2];
    const float* w2  = (const float*)d_in[3];
    const float* b2  = (const float*)d_in[4];
    const float* rw1 = (const float*)d_in[5];
    const float* rb1 = (const float*)d_in[6];
    const float* rw2 = (const float*)d_in[7];
    const float* rb2 = (const float*)d_in[8];
    const int*   nbr = (const int*)  d_in[9];
    float* out = (float*)d_out;

    const int SMEM_G = (64 + 128) * 132 * (int)sizeof(float);             // 101376 B
    const int SMEM_S = (2 * 128 * 72 + 2 * 64 * 72) * (int)sizeof(float); // 110592 B
    static bool attr_done = false;
    if (!attr_done) {
        cudaFuncSetAttribute(gemm1_kernel, cudaFuncAttributeMaxDynamicSharedMemorySize, SMEM_G);
        cudaFuncSetAttribute(gemm2_kernel, cudaFuncAttributeMaxDynamicSharedMemorySize, SMEM_G);
        cudaFuncSetAttribute(sconv_mma<0>, cudaFuncAttributeMaxDynamicSharedMemorySize, SMEM_S);
        cudaFuncSetAttribute(sconv_mma<1>, cudaFuncAttributeMaxDynamicSharedMemorySize, SMEM_S);
        attr_done = true;
    }

    const int gridG = NPAD / 64;    // 1564
    const int gridS = NPAD / 128;   // 782

    prep_weights<<<432, 256>>>(w1, w2, rw1, rw2);
    gemm1_kernel<<<gridG, 256, SMEM_G>>>(x, b1);
    sconv_mma<0><<<gridS, 256, SMEM_S>>>(nbr, rb1);
    sconv_mma<1><<<gridS, 256, SMEM_S>>>(nbr, rb2);
    gemm2_kernel<<<gridG, 256, SMEM_G>>>(x, b2, out);
}

// round 12
// speedup vs baseline: 1.6512x; 1.2556x over previous
#include <cuda_runtime.h>
#include <cstdint>
#include <mma.h>

using namespace nvcuda;

static constexpr int NP   = 100000;     // points
static constexpr int NPAD = 100096;     // multiple of 128 (782 * 128)
static constexpr int CH   = 128;
static constexpr int HH   = 64;

// Scratch (device globals; referenced ONLY inside device code — never from host)
__device__ float g_y  [(size_t)NPAD * CH];   // y = x@w1 + b1   (tf32-rounded)
__device__ float g_r1 [(size_t)NPAD * HH];   // relu(sconv1)    (tf32-rounded)
__device__ float g_r2 [(size_t)NPAD * HH];   // relu(sconv2)    (tf32-rounded)
__device__ float g_w1r [CH * CH];            // rna(w1)
__device__ float g_w2r [CH * CH];            // rna(w2)
__device__ float g_rwp1[27 * HH * HH];       // rna(rw1) TRANSPOSED: [k][d][c]
__device__ float g_rwp2[27 * HH * HH];       // rna(rw2) TRANSPOSED: [k][d][c]

// ---------------------------------------------------------------------------
// helpers
// ---------------------------------------------------------------------------
__device__ __forceinline__ unsigned smem_u32(const void* p) {
    return (unsigned)__cvta_generic_to_shared(p);
}
__device__ __forceinline__ void cp16(unsigned dst, const void* src, int src_size) {
    asm volatile("cp.async.cg.shared.global [%0], [%1], 16, %2;"
                 :: "r"(dst), "l"(src), "r"(src_size));
}
__device__ __forceinline__ void cp_commit() { asm volatile("cp.async.commit_group;"); }
template <int N>
__device__ __forceinline__ void cp_wait() {
    asm volatile("cp.async.wait_group %0;" :: "n"(N));
}
__device__ __forceinline__ float rna_tf32(float x) {
    unsigned r;
    asm("cvt.rna.tf32.f32 %0, %1;" : "=r"(r) : "f"(x));
    return __uint_as_float(r);
}
__device__ __forceinline__ void mma_tf32(float* d, const uint32_t* a, const uint32_t* b) {
    asm volatile(
        "mma.sync.aligned.m16n8k8.row.col.f32.tf32.tf32.f32 "
        "{%0,%1,%2,%3}, {%4,%5,%6,%7}, {%8,%9}, {%0,%1,%2,%3};"
        : "+f"(d[0]), "+f"(d[1]), "+f"(d[2]), "+f"(d[3])
        : "r"(a[0]), "r"(a[1]), "r"(a[2]), "r"(a[3]), "r"(b[0]), "r"(b[1]));
}

// ---------------------------------------------------------------------------
// prologue: rna weight copies; sconv weights transposed to [k][d][c]
// ---------------------------------------------------------------------------
__global__ __launch_bounds__(256) void prep_weights(
    const float* __restrict__ w1, const float* __restrict__ w2,
    const float* __restrict__ rw1, const float* __restrict__ rw2)
{
    int j = blockIdx.x * 256 + threadIdx.x;
    if (j < CH * CH) {
        g_w1r[j] = rna_tf32(w1[j]);
        g_w2r[j] = rna_tf32(w2[j]);
    }
    if (j < 27 * HH * HH) {
        int k = j >> 12, d = (j >> 6) & 63, c = j & 63;
        int src = (k << 12) + (c << 6) + d;
        g_rwp1[j] = rna_tf32(rw1[src]);
        g_rwp2[j] = rna_tf32(rw2[src]);
    }
}

// ---------------------------------------------------------------------------
// GEMM1 (R11-proven): g_y[n,:] = rna( x[n,:] @ rna(w1) + b1 )
// ---------------------------------------------------------------------------
__global__ __launch_bounds__(256) void gemm1_kernel(
    const float* __restrict__ x, const float* __restrict__ b1)
{
    extern __shared__ float smem[];
    float* As = smem;               // 64 x 132
    float* Bs = smem + 64 * 132;    // 128 x 132

    const int tid = threadIdx.x;
    const int rowBase = blockIdx.x * 64;

    #pragma unroll
    for (int i = 0; i < 8; i++) {
        int j = tid + i * 256;
        int row = j >> 5, seg = j & 31;
        int n = rowBase + row;
        cp16(smem_u32(As + row * 132 + seg * 4), x + (size_t)n * 128 + seg * 4,
             (n < NP) ? 16 : 0);
    }
    #pragma unroll
    for (int i = 0; i < 16; i++) {
        int j = tid + i * 256;
        int row = j >> 5, seg = j & 31;
        cp16(smem_u32(Bs + row * 132 + seg * 4), g_w1r + j * 4, 16);
    }
    cp_commit();
    cp_wait<0>();
    __syncthreads();

    const int warp = tid >> 5;
    const int mw = warp >> 1, nw = warp & 1;

    wmma::fragment<wmma::accumulator, 16, 16, 8, float> c[4];
    #pragma unroll
    for (int f = 0; f < 4; f++) wmma::fill_fragment(c[f], 0.f);

    #pragma unroll
    for (int kk = 0; kk < 16; kk++) {
        wmma::fragment<wmma::matrix_a, 16, 16, 8, wmma::precision::tf32, wmma::row_major> a;
        wmma::load_matrix_sync(a, As + (mw * 16) * 132 + kk * 8, 132);
        #pragma unroll
        for (int f = 0; f < 4; f++) {
            wmma::fragment<wmma::matrix_b, 16, 16, 8, wmma::precision::tf32, wmma::row_major> b;
            wmma::load_matrix_sync(b, Bs + (kk * 8) * 132 + nw * 64 + f * 16, 132);
            wmma::mma_sync(c[f], a, b, c[f]);
        }
    }
    __syncthreads();
    #pragma unroll
    for (int f = 0; f < 4; f++)
        wmma::store_matrix_sync(As + (mw * 16) * 132 + nw * 64 + f * 16, c[f], 132,
                                wmma::mem_row_major);
    __syncthreads();

    #pragma unroll
    for (int i = 0; i < 8; i++) {
        int j = tid + i * 256;
        int row = j >> 5, seg = j & 31;
        int n = rowBase + row;
        float4 v  = *(float4*)(As + row * 132 + seg * 4);
        float4 bb = *(const float4*)(b1 + seg * 4);
        v.x = rna_tf32(v.x + bb.x);
        v.y = rna_tf32(v.y + bb.y);
        v.z = rna_tf32(v.z + bb.z);
        v.w = rna_tf32(v.w + bb.w);
        *(float4*)(g_y + (size_t)n * 128 + seg * 4) = v;
    }
}

// ---------------------------------------------------------------------------
// sconv (raw mma.sync m16n8k8 tf32) — R11 math/layout EXACTLY; only the fill
// lane mappings changed for L1tex wavefront coalescing:
//   old: each warp cp instr touched ~32 distinct 128B lines (1 wf per cp16)
//   new: row = tid>>2, quarter = tid&3, 4 x 64B segments per row
//        -> each warp cp instr covers 8 rows x contiguous 64B = 8 lines/wf.
// A: 2048 -> 512 wf/CTA-iter, B: 1024 -> 256. Same bytes, same smem image.
// ---------------------------------------------------------------------------
template <int SRC>
__global__ __launch_bounds__(256, 2) void sconv_mma(
    const int*   __restrict__ nbr,
    const float* __restrict__ rb)
{
    extern __shared__ float sm[];

    const float* feat = (SRC == 0) ? g_y : g_r1;
    const float* rwp  = (SRC == 0) ? g_rwp1 : g_rwp2;
    float*       outp = (SRC == 0) ? g_r1 : g_r2;
    const int    ldf  = (SRC == 0) ? 128 : 64;

    const int tid  = threadIdx.x;
    const int lane = tid & 31;
    const int warp = tid >> 5;
    const int wrow = warp >> 1;          // 0..3 -> rows 32*wrow
    const int wcol = warp & 1;           // 0..1 -> cols 32*wcol
    const int lr   = lane >> 2;          // 0..7
    const int la3  = lane & 3;           // 0..3
    const int rowBase = blockIdx.x * 128;

    // fill assignments (wavefront-coalesced): 4 lanes per row
    const int frow = tid >> 2;           // 0..63 (+64 for second round of A)
    const int fq   = tid & 3;            // 16B quarter within a 64B segment

    auto ldIdx2 = [&](int kk, int* o) {
        #pragma unroll
        for (int rr = 0; rr < 2; rr++) {
            int n = rowBase + frow + rr * 64;
            o[rr] = (n < NP) ? __ldg(nbr + (size_t)kk * NP + n) : -1;
        }
    };
    auto fillA = [&](int buf, const int* idx2) {
        #pragma unroll
        for (int rr = 0; rr < 2; rr++) {
            int row = frow + rr * 64;
            int idx = idx2[rr];
            int sz  = (idx >= 0) ? 16 : 0;
            const float* src = feat + (size_t)(idx < 0 ? 0 : idx) * ldf + fq * 4;
            float* dst = sm + buf * 9216 + row * 72 + fq * 4;
            #pragma unroll
            for (int s = 0; s < 4; s++)      // 64B segments: 8 rows/warp-instr
                cp16(smem_u32(dst + s * 16), src + s * 16, sz);
        }
    };
    auto fillB = [&](int kk, int buf) {
        const float* src = rwp + (size_t)kk * 4096 + frow * 64 + fq * 4;
        float* dst = sm + 18432 + buf * 4608 + frow * 72 + fq * 4;
        #pragma unroll
        for (int s = 0; s < 4; s++)
            cp16(smem_u32(dst + s * 16), src + s * 16, 16);
    };

    float acc[2][4][4];
    #pragma unroll
    for (int mt = 0; mt < 2; mt++)
        #pragma unroll
        for (int nt = 0; nt < 4; nt++)
            #pragma unroll
            for (int q = 0; q < 4; q++) acc[mt][nt][q] = 0.f;

    int rr4[4];
    #pragma unroll
    for (int i = 0; i < 4; i++) rr4[i] = wrow * 32 + lr + i * 8;

    int idxNxt[2];
    ldIdx2(0, idxNxt);
    fillA(0, idxNxt);
    fillB(0, 0);
    cp_commit();
    ldIdx2(1, idxNxt);

    for (int kk = 0; kk < 27; kk++) {
        const int buf = kk & 1;
        cp_wait<0>();                    // stage kk copies (this thread) done
        __syncthreads();                 // all copies visible; prev readers done

        if (kk + 1 < 27) {               // fills AFTER barrier -> safe recycle
            fillA(buf ^ 1, idxNxt);
            fillB(kk + 1, buf ^ 1);
            cp_commit();
            if (kk + 2 < 27) ldIdx2(kk + 2, idxNxt);
        }

        const float* Ab = sm + buf * 9216;
        const float* Bb = sm + 18432 + buf * 4608;

        #pragma unroll
        for (int k8 = 0; k8 < 8; k8++) {
            uint32_t af[4][2];
            #pragma unroll
            for (int i = 0; i < 4; i++) {
                float2 t = *(const float2*)(Ab + rr4[i] * 72 + k8 * 8 + 2 * la3);
                af[i][0] = __float_as_uint(t.x);
                af[i][1] = __float_as_uint(t.y);
            }
            uint32_t bf[4][2];
            #pragma unroll
            for (int nt = 0; nt < 4; nt++) {
                int n = wcol * 32 + nt * 8 + lr;
                float2 t = *(const float2*)(Bb + n * 72 + k8 * 8 + 2 * la3);
                bf[nt][0] = __float_as_uint(t.x);
                bf[nt][1] = __float_as_uint(t.y);
            }
            #pragma unroll
            for (int mt = 0; mt < 2; mt++) {
                uint32_t a[4] = { af[2 * mt][0], af[2 * mt + 1][0],
                                  af[2 * mt][1], af[2 * mt + 1][1] };
                #pragma unroll
                for (int nt = 0; nt < 4; nt++)
                    mma_tf32(acc[mt][nt], a, bf[nt]);
            }
        }
    }

    // epilogue: bias + relu + rna, register -> global
    #pragma unroll
    for (int nt = 0; nt < 4; nt++) {
        int cc = wcol * 32 + nt * 8 + 2 * la3;
        float rb0 = rb[cc], rb1 = rb[cc + 1];
        #pragma unroll
        for (int mt = 0; mt < 2; mt++) {
            int r0 = rowBase + wrow * 32 + mt * 16 + lr;
            float2 v0, v1;
            v0.x = rna_tf32(fmaxf(acc[mt][nt][0] + rb0, 0.f));
            v0.y = rna_tf32(fmaxf(acc[mt][nt][1] + rb1, 0.f));
            v1.x = rna_tf32(fmaxf(acc[mt][nt][2] + rb0, 0.f));
            v1.y = rna_tf32(fmaxf(acc[mt][nt][3] + rb1, 0.f));
            *(float2*)(outp + (size_t)r0 * 64 + cc)       = v0;
            *(float2*)(outp + (size_t)(r0 + 8) * 64 + cc) = v1;
        }
    }
}

// ---------------------------------------------------------------------------
// GEMM2 (R11-proven): out = x + concat(rna(r2+2*yc), yt) @ rna(w2) + b2
// ---------------------------------------------------------------------------
__global__ __launch_bounds__(256) void gemm2_kernel(
    const float* __restrict__ x, const float* __restrict__ b2,
    float* __restrict__ out)
{
    extern __shared__ float smem[];
    float* As = smem;
    float* Bs = smem + 64 * 132;

    const int tid = threadIdx.x;
    const int rowBase = blockIdx.x * 64;

    #pragma unroll
    for (int i = 0; i < 16; i++) {
        int j = tid + i * 256;
        int row = j >> 5, seg = j & 31;
        cp16(smem_u32(Bs + row * 132 + seg * 4), g_w2r + j * 4, 16);
    }
    cp_commit();

    #pragma unroll
    for (int i = 0; i < 8; i++) {
        int j = tid + i * 256;
        int row = j >> 5, seg = j & 31;
        int n = rowBase + row;
        float4 v;
        if (seg < 16) {
            float4 r = *(const float4*)(g_r2 + (size_t)n * 64  + seg * 4);
            float4 y = *(const float4*)(g_y  + (size_t)n * 128 + seg * 4);
            v.x = rna_tf32(fmaf(2.f, y.x, r.x));
            v.y = rna_tf32(fmaf(2.f, y.y, r.y));
            v.z = rna_tf32(fmaf(2.f, y.z, r.z));
            v.w = rna_tf32(fmaf(2.f, y.w, r.w));
        } else {
            v = *(const float4*)(g_y + (size_t)n * 128 + seg * 4);
        }
        *(float4*)(As + row * 132 + seg * 4) = v;
    }
    cp_wait<0>();
    __syncthreads();

    const int warp = tid >> 5;
    const int mw = warp >> 1, nw = warp & 1;

    wmma::fragment<wmma::accumulator, 16, 16, 8, float> c[4];
    #pragma unroll
    for (int f = 0; f < 4; f++) wmma::fill_fragment(c[f], 0.f);

    #pragma unroll
    for (int kk = 0; kk < 16; kk++) {
        wmma::fragment<wmma::matrix_a, 16, 16, 8, wmma::precision::tf32, wmma::row_major> a;
        wmma::load_matrix_sync(a, As + (mw * 16) * 132 + kk * 8, 132);
        #pragma unroll
        for (int f = 0; f < 4; f++) {
            wmma::fragment<wmma::matrix_b, 16, 16, 8, wmma::precision::tf32, wmma::row_major> b;
            wmma::load_matrix_sync(b, Bs + (kk * 8) * 132 + nw * 64 + f * 16, 132);
            wmma::mma_sync(c[f], a, b, c[f]);
        }
    }
    __syncthreads();
    #pragma unroll
    for (int f = 0; f < 4; f++)
        wmma::store_matrix_sync(As + (mw * 16) * 132 + nw * 64 + f * 16, c[f], 132,
                                wmma::mem_row_major);
    __syncthreads();

    #pragma unroll
    for (int i = 0; i < 8; i++) {
        int j = tid + i * 256;
        int row = j >> 5, seg = j & 31;
        int n = rowBase + row;
        if (n < NP) {
            float4 v  = *(float4*)(As + row * 132 + seg * 4);
            float4 bb = *(const float4*)(b2 + seg * 4);
            float4 xr = *(const float4*)(x + (size_t)n * 128 + seg * 4);
            v.x += bb.x + xr.x;
            v.y += bb.y + xr.y;
            v.z += bb.z + xr.z;
            v.w += bb.w + xr.w;
            *(float4*)(out + (size_t)n * 128 + seg * 4) = v;
        }
    }
}

// ---------------------------------------------------------------------------
extern "C" void kernel_launch(void* const* d_in, const int* in_sizes, int n_in,
                              void* d_out, int out_size)
{
    const float* x   = (const float*)d_in[0];
    const float* w1  = (const float*)d_in[1];
    const float* b1  = (const float*)d_in[2];
    const float* w2  = (const float*)d_in[3];
    const float* b2  = (const float*)d_in[4];
    const float* rw1 = (const float*)d_in[5];
    const float* rb1 = (const float*)d_in[6];
    const float* rw2 = (const float*)d_in[7];
    const float* rb2 = (const float*)d_in[8];
    const int*   nbr = (const int*)  d_in[9];
    float* out = (float*)d_out;

    const int SMEM_G = (64 + 128) * 132 * (int)sizeof(float);             // 101376 B
    const int SMEM_S = (2 * 128 * 72 + 2 * 64 * 72) * (int)sizeof(float); // 110592 B
    static bool attr_done = false;
    if (!attr_done) {
        cudaFuncSetAttribute(gemm1_kernel, cudaFuncAttributeMaxDynamicSharedMemorySize, SMEM_G);
        cudaFuncSetAttribute(gemm2_kernel, cudaFuncAttributeMaxDynamicSharedMemorySize, SMEM_G);
        cudaFuncSetAttribute(sconv_mma<0>, cudaFuncAttributeMaxDynamicSharedMemorySize, SMEM_S);
        cudaFuncSetAttribute(sconv_mma<1>, cudaFuncAttributeMaxDynamicSharedMemorySize, SMEM_S);
        attr_done = true;
    }

    const int gridG = NPAD / 64;    // 1564
    const int gridS = NPAD / 128;   // 782

    prep_weights<<<432, 256>>>(w1, w2, rw1, rw2);
    gemm1_kernel<<<gridG, 256, SMEM_G>>>(x, b1);
    sconv_mma<0><<<gridS, 256, SMEM_S>>>(nbr, rb1);
    sconv_mma<1><<<gridS, 256, SMEM_S>>>(nbr, rb2);
    gemm2_kernel<<<gridG, 256, SMEM_G>>>(x, b2, out);
}